// round 10
// baseline (speedup 1.0000x reference)
#include <cuda_runtime.h>
#include <cstdint>

#define MAXB 65536
#define BLK 256
#define EPT 4
#define TILE (BLK * EPT)                 // 1024 batches per scan tile
#define MAXG ((MAXB + TILE - 1) / TILE)  // 64 tiles

// Scratch (allocation-free __device__ globals).
// g_meta[b]: os_loc(20) | ns_loc(20)<<20 | f(10)<<40   (offsets local to tile)
// g_agg[t]:  packed tile totals: span_sum(lo32) | filter_sum(hi32)
__device__ unsigned long long g_meta[MAXB];
__device__ unsigned long long g_agg[MAXG];

__device__ __forceinline__ unsigned long long pack2(int span, int filt) {
    return (unsigned long long)(unsigned int)span |
           ((unsigned long long)(unsigned int)filt << 32);
}

// ---------------------------------------------------------------------------
// Scan kernel: grid = G (<=64). Per-tile local exclusive scan + tile totals.
// No cross-block communication: deterministic, replay-safe.
// ---------------------------------------------------------------------------
__global__ void __launch_bounds__(BLK) scan_kernel(
        const int* __restrict__ al, const int* __restrict__ alf, int B) {
    __shared__ unsigned long long s_wexcl[BLK / 32];
    __shared__ unsigned long long s_wtot[BLK / 32];

    const int t = threadIdx.x, lane = t & 31, wid = t >> 5;
    const int bid = blockIdx.x;
    const int i0 = bid * TILE + t * EPT;

    unsigned long long p[EPT];
    if (i0 + 3 < B) {
        int4 a = *(const int4*)(al + i0);
        int4 f = *(const int4*)(alf + i0);
        p[0] = pack2(a.x + 1, f.x);
        p[1] = pack2(a.y + 1, f.y);
        p[2] = pack2(a.z + 1, f.z);
        p[3] = pack2(a.w + 1, f.w);
    } else {
        #pragma unroll
        for (int k = 0; k < EPT; k++) {
            int i = i0 + k;
            p[k] = (i < B) ? pack2(al[i] + 1, alf[i]) : 0ull;
        }
    }
    unsigned long long tot = p[0] + p[1] + p[2] + p[3];

    unsigned long long incl = tot;
    #pragma unroll
    for (int o = 1; o < 32; o <<= 1) {
        unsigned long long n = __shfl_up_sync(0xffffffffu, incl, o);
        if (lane >= o) incl += n;
    }
    unsigned long long texcl = incl - tot;
    if (lane == 31) s_wtot[wid] = incl;
    __syncthreads();

    if (wid == 0) {
        unsigned long long v = (lane < BLK / 32) ? s_wtot[lane] : 0ull;
        unsigned long long inc = v;
        #pragma unroll
        for (int o = 1; o < BLK / 32; o <<= 1) {
            unsigned long long n = __shfl_up_sync(0xffffffffu, inc, o);
            if (lane >= o) inc += n;
        }
        if (lane < BLK / 32) s_wexcl[lane] = inc - v;
        if (lane == BLK / 32 - 1) g_agg[bid] = inc;   // tile total
    }
    __syncthreads();

    unsigned long long run = s_wexcl[wid] + texcl;    // local exclusive prefix
    #pragma unroll
    for (int k = 0; k < EPT; k++) {
        int i = i0 + k;
        if (i < B) {
            unsigned long long os = run & 0xffffffffull;   // <2^20
            unsigned long long ns = run >> 32;             // <2^20
            unsigned long long fv = p[k] >> 32;            // <2^10
            g_meta[i] = os | (ns << 20) | (fv << 40);
            run += p[k];
        }
    }
}

// ---------------------------------------------------------------------------
// Copy body template: NS = number of float4 slots per thread (covers NS*128
// floats per warp). Loads are scalar (src arbitrary align) but batched for
// MLP; stores are 16B-aligned STG.128 on the peeled dst.
// ---------------------------------------------------------------------------
template<int NS>
__device__ __forceinline__ void vec_body(const float* __restrict__ s,
                                         float* __restrict__ d,
                                         int nb4, int tail, int lane) {
    float x[NS * 4];
    #pragma unroll
    for (int k = 0; k < NS; k++) {
        int q = lane + k * 32;             // float4 index
        bool pv = q < nb4;
        #pragma unroll
        for (int e = 0; e < 4; e++)
            x[k * 4 + e] = pv ? __ldcs(s + q * 4 + e) : 0.0f;
    }
    const float* st = s + nb4 * 4;
    float xt = (lane < tail) ? __ldcs(st + lane) : 0.0f;

    #pragma unroll
    for (int k = 0; k < NS; k++) {
        int q = lane + k * 32;
        if (q < nb4)
            __stcs(reinterpret_cast<float4*>(d) + q,
                   make_float4(x[k*4], x[k*4+1], x[k*4+2], x[k*4+3]));
    }
    if (lane < tail) __stcs(d + nb4 * 4 + lane, xt);
}

// ---------------------------------------------------------------------------
// Copy: one warp per batch. Tile base via 64-aggregate butterfly reduce,
// one u64 metadata broadcast, dst-aligned vectorized streaming copy with a
// warp-uniform f-ladder so short batches issue few instructions.
// ---------------------------------------------------------------------------
__global__ void __launch_bounds__(256) copy_kernel(
        const float* __restrict__ src, float* __restrict__ out, int B) {
    int w    = (blockIdx.x * blockDim.x + threadIdx.x) >> 5;
    int lane = threadIdx.x & 31;
    if (w >= B) return;

    int tile = w >> 10;                       // TILE = 1024

    unsigned long long a0 = g_agg[lane];
    unsigned long long a1 = g_agg[lane + 32];
    unsigned long long v = 0;
    if (lane      < tile) v += a0;
    if (lane + 32 < tile) v += a1;
    #pragma unroll
    for (int o = 16; o > 0; o >>= 1)
        v += __shfl_xor_sync(0xffffffffu, v, o);

    unsigned long long m = g_meta[w];          // broadcast 8B load
    int f = (int)(m >> 40);
    if (f == 0) return;
    const float* s = src + (int)(v & 0xffffffffull) + (int)(m & 0xfffffull);
    float*       d = out + (int)(v >> 32)          + (int)((m >> 20) & 0xfffffull);

    // Peel to 16B-align dst (dst is always 4B-aligned).
    int mis  = ((int)((uintptr_t)d >> 2)) & 3;         // floats past 16B boundary
    int head = (4 - mis) & 3;
    if (head > f) head = f;
    if (lane < head) __stcs(d + lane, __ldcs(s + lane));
    s += head; d += head; f -= head;

    int nb4  = f >> 2;                                  // float4 count (<=128)
    int tail = f & 3;

    if (nb4 <= 32) {
        vec_body<1>(s, d, nb4, tail, lane);
    } else if (nb4 <= 64) {
        vec_body<2>(s, d, nb4, tail, lane);
    } else if (nb4 <= 96) {
        vec_body<3>(s, d, nb4, tail, lane);
    } else {
        vec_body<4>(s, d, nb4, tail, lane);
    }
}

// ---------------------------------------------------------------------------
// Launch: 2 kernels, no memset, no cross-block waits anywhere.
// ---------------------------------------------------------------------------
extern "C" void kernel_launch(void* const* d_in, const int* in_sizes, int n_in,
                              void* d_out, int out_size) {
    const float* tgt_cache_loc = (const float*)d_in[0];
    const int*   accept_length = (const int*)d_in[1];
    const int*   accept_filter = (const int*)d_in[2];
    (void)n_in; (void)out_size;

    int B = in_sizes[1];
    int G = (B + TILE - 1) / TILE;

    scan_kernel<<<G, BLK>>>(accept_length, accept_filter, B);

    int blocks = (B * 32 + 255) / 256;    // one warp per batch
    copy_kernel<<<blocks, 256>>>(tgt_cache_loc, (float*)d_out, B);
}

// round 11
// speedup vs baseline: 1.0769x; 1.0769x over previous
#include <cuda_runtime.h>
#include <cstdint>

#define MAXB 65536
#define BLK 256
#define EPT 4
#define TILE (BLK * EPT)                 // 1024 batches per scan tile
#define MAXG ((MAXB + TILE - 1) / TILE)  // 64 tiles

// Scratch (allocation-free __device__ globals).
// g_meta[b]: os_loc(20) | ns_loc(20)<<20 | f(10)<<40   (offsets local to tile)
// g_agg[t]:  packed tile totals: span_sum(lo32) | filter_sum(hi32)
__device__ unsigned long long g_meta[MAXB];
__device__ unsigned long long g_agg[MAXG];

__device__ __forceinline__ unsigned long long pack2(int span, int filt) {
    return (unsigned long long)(unsigned int)span |
           ((unsigned long long)(unsigned int)filt << 32);
}

// ---------------------------------------------------------------------------
// Scan kernel: grid = G (<=64). Per-tile local exclusive scan + tile totals.
// No cross-block communication: deterministic, replay-safe.
// ---------------------------------------------------------------------------
__global__ void __launch_bounds__(BLK) scan_kernel(
        const int* __restrict__ al, const int* __restrict__ alf, int B) {
    __shared__ unsigned long long s_wexcl[BLK / 32];
    __shared__ unsigned long long s_wtot[BLK / 32];

    const int t = threadIdx.x, lane = t & 31, wid = t >> 5;
    const int bid = blockIdx.x;
    const int i0 = bid * TILE + t * EPT;

    unsigned long long p[EPT];
    if (i0 + 3 < B) {
        int4 a = *(const int4*)(al + i0);
        int4 f = *(const int4*)(alf + i0);
        p[0] = pack2(a.x + 1, f.x);
        p[1] = pack2(a.y + 1, f.y);
        p[2] = pack2(a.z + 1, f.z);
        p[3] = pack2(a.w + 1, f.w);
    } else {
        #pragma unroll
        for (int k = 0; k < EPT; k++) {
            int i = i0 + k;
            p[k] = (i < B) ? pack2(al[i] + 1, alf[i]) : 0ull;
        }
    }
    unsigned long long tot = p[0] + p[1] + p[2] + p[3];

    unsigned long long incl = tot;
    #pragma unroll
    for (int o = 1; o < 32; o <<= 1) {
        unsigned long long n = __shfl_up_sync(0xffffffffu, incl, o);
        if (lane >= o) incl += n;
    }
    unsigned long long texcl = incl - tot;
    if (lane == 31) s_wtot[wid] = incl;
    __syncthreads();

    if (wid == 0) {
        unsigned long long v = (lane < BLK / 32) ? s_wtot[lane] : 0ull;
        unsigned long long inc = v;
        #pragma unroll
        for (int o = 1; o < BLK / 32; o <<= 1) {
            unsigned long long n = __shfl_up_sync(0xffffffffu, inc, o);
            if (lane >= o) inc += n;
        }
        if (lane < BLK / 32) s_wexcl[lane] = inc - v;
        if (lane == BLK / 32 - 1) g_agg[bid] = inc;   // tile total
    }
    __syncthreads();

    unsigned long long run = s_wexcl[wid] + texcl;    // local exclusive prefix
    #pragma unroll
    for (int k = 0; k < EPT; k++) {
        int i = i0 + k;
        if (i < B) {
            unsigned long long os = run & 0xffffffffull;   // <2^20
            unsigned long long ns = run >> 32;             // <2^20
            unsigned long long fv = p[k] >> 32;            // <2^10
            g_meta[i] = os | (ns << 20) | (fv << 40);
            run += p[k];
        }
    }
}

// ---------------------------------------------------------------------------
// Copy body: NS lane-contiguous 32-element chunks. Every LDG/STG instruction
// covers exactly 128B (one L1 wavefront). All loads issued before any store
// (MLP = NS).
// ---------------------------------------------------------------------------
template<int NS>
__device__ __forceinline__ void chunk_body(const float* __restrict__ s,
                                           float* __restrict__ d,
                                           int f, int lane) {
    float x[NS];
    #pragma unroll
    for (int k = 0; k < NS; k++) {
        int i = lane + k * 32;
        x[k] = (i < f) ? __ldcs(s + i) : 0.0f;
    }
    #pragma unroll
    for (int k = 0; k < NS; k++) {
        int i = lane + k * 32;
        if (i < f) __stcs(d + i, x[k]);
    }
}

// ---------------------------------------------------------------------------
// Copy: one warp per batch. Tile base via 64-aggregate butterfly reduce,
// one u64 metadata broadcast, then an f-ladder (even chunk counts) so short
// batches issue few memory instructions — all perfectly coalesced.
// ---------------------------------------------------------------------------
__global__ void __launch_bounds__(256) copy_kernel(
        const float* __restrict__ src, float* __restrict__ out, int B) {
    int w    = (blockIdx.x * blockDim.x + threadIdx.x) >> 5;
    int lane = threadIdx.x & 31;
    if (w >= B) return;

    unsigned long long m = g_meta[w];          // broadcast 8B load
    int tile = w >> 10;                        // TILE = 1024

    unsigned long long a0 = g_agg[lane];
    unsigned long long a1 = g_agg[lane + 32];
    unsigned long long v = 0;
    if (lane      < tile) v += a0;
    if (lane + 32 < tile) v += a1;
    #pragma unroll
    for (int o = 16; o > 0; o >>= 1)
        v += __shfl_xor_sync(0xffffffffu, v, o);

    int f = (int)(m >> 40);
    if (f == 0) return;
    const float* s = src + (int)(v & 0xffffffffull) + (int)(m & 0xfffffull);
    float*       d = out + (int)(v >> 32)          + (int)((m >> 20) & 0xfffffull);

    // Ladder on chunk count, rounded up to even (f <= 512 -> nc <= 16).
    switch ((f + 63) >> 6) {                   // ceil(f/64) in 1..8
        case 1: chunk_body<2>(s, d, f, lane); break;
        case 2: chunk_body<4>(s, d, f, lane); break;
        case 3: chunk_body<6>(s, d, f, lane); break;
        case 4: chunk_body<8>(s, d, f, lane); break;
        case 5: chunk_body<10>(s, d, f, lane); break;
        case 6: chunk_body<12>(s, d, f, lane); break;
        case 7: chunk_body<14>(s, d, f, lane); break;
        default: chunk_body<16>(s, d, f, lane); break;
    }
}

// ---------------------------------------------------------------------------
// Launch: 2 kernels, no memset, no cross-block waits anywhere.
// ---------------------------------------------------------------------------
extern "C" void kernel_launch(void* const* d_in, const int* in_sizes, int n_in,
                              void* d_out, int out_size) {
    const float* tgt_cache_loc = (const float*)d_in[0];
    const int*   accept_length = (const int*)d_in[1];
    const int*   accept_filter = (const int*)d_in[2];
    (void)n_in; (void)out_size;

    int B = in_sizes[1];
    int G = (B + TILE - 1) / TILE;

    scan_kernel<<<G, BLK>>>(accept_length, accept_filter, B);

    int blocks = (B * 32 + 255) / 256;    // one warp per batch
    copy_kernel<<<blocks, 256>>>(tgt_cache_loc, (float*)d_out, B);
}